// round 12
// baseline (speedup 1.0000x reference)
#include <cuda_runtime.h>
#include <cstdint>

// Problem constants: SEQ=1024, BATCH=512, IN=128, HID=256, alpha=0.2
#define S_  1024
#define B_  512
#define IN_ 128
#define H_  256

typedef unsigned long long u64;

__device__ __forceinline__ u64 ffma2(u64 a, u64 b, u64 c) {
    u64 d;
    asm("fma.rn.f32x2 %0, %1, %2, %3;" : "=l"(d) : "l"(a), "l"(b), "l"(c));
    return d;
}
__device__ __forceinline__ u64 pack2(float x, float y) {
    u64 r;
    asm("mov.b64 %0, {%1, %2};" : "=l"(r) : "f"(x), "f"(y));
    return r;
}
__device__ __forceinline__ float2 unpack2(u64 v) {
    float2 r;
    asm("mov.b64 {%0, %1}, %2;" : "=f"(r.x), "=f"(r.y) : "l"(v));
    return r;
}

// ======================= Phase 1: x_proj GEMM ============================
// (unchanged — ~0.65 ms)
// out[(s*B + b)*H + h] = input[s,b,:] . W_in[:,h] + b_in[h] + b_hh[h]
// [M=524288, K=128] @ [128, 256]. Chunked-K (KC=16, 8 chunks) double-
// buffered; block tile 128x64, 256 threads, thread tile 4 row-pairs x 4
// cols (f32x2). Static smem 25KB, 3 blocks/SM.

#define XP_KC   16
#define XP_AST  132

__global__ void __launch_bounds__(256, 3) xproj_kernel(
    const float* __restrict__ input, const float* __restrict__ Win,
    const float* __restrict__ bin, const float* __restrict__ bhh,
    float* __restrict__ out)
{
    __shared__ float As[2][XP_KC][XP_AST];
    __shared__ float Bs[2][XP_KC][64];

    const int t = threadIdx.x;
    const size_t rowBase = (size_t)blockIdx.x * 128;
    const int colBase = blockIdx.y * 64;

    const int tx = t & 15, ty = t >> 4;
    const int m0 = ty * 8, n0 = tx * 4;

    const int rA = t >> 2;
    const int kq = t & 3;
    const int bk = t >> 4;
    const int bn = (t & 15) * 4;

    const float* aSrc0 = input + (rowBase + rA) * IN_ + kq * 4;
    const float* aSrc1 = input + (rowBase + rA + 64) * IN_ + kq * 4;
    const float* bSrc  = Win + (size_t)bk * H_ + colBase + bn;

    u64 acc[4][4];
    {
        float4 bi = *(const float4*)(bin + colBase + n0);
        float4 bh = *(const float4*)(bhh + colBase + n0);
        float bias[4] = {bi.x + bh.x, bi.y + bh.y, bi.z + bh.z, bi.w + bh.w};
        #pragma unroll
        for (int j = 0; j < 4; j++) {
            u64 bb = pack2(bias[j], bias[j]);
            #pragma unroll
            for (int mp = 0; mp < 4; mp++) acc[mp][j] = bb;
        }
    }

    {
        float4 a0 = *(const float4*)(aSrc0);
        float4 a1 = *(const float4*)(aSrc1);
        float4 b  = *(const float4*)(bSrc);
        #pragma unroll
        for (int j = 0; j < 4; j++) {
            As[0][kq * 4 + j][rA]      = ((const float*)&a0)[j];
            As[0][kq * 4 + j][rA + 64] = ((const float*)&a1)[j];
        }
        *(float4*)&Bs[0][bk][bn] = b;
    }
    __syncthreads();

    #pragma unroll 1
    for (int c = 0; c < 8; c++) {
        const int cur = c & 1, nxt = cur ^ 1;
        float4 a0, a1, b;
        if (c < 7) {
            a0 = *(const float4*)(aSrc0 + (c + 1) * XP_KC);
            a1 = *(const float4*)(aSrc1 + (c + 1) * XP_KC);
            b  = *(const float4*)(bSrc + (size_t)(c + 1) * XP_KC * H_);
        }

        #pragma unroll
        for (int k = 0; k < XP_KC; k++) {
            ulonglong2 ap0 = *(const ulonglong2*)&As[cur][k][m0];
            ulonglong2 ap1 = *(const ulonglong2*)&As[cur][k][m0 + 4];
            u64 av[4] = {ap0.x, ap0.y, ap1.x, ap1.y};
            float4 b4 = *(const float4*)&Bs[cur][k][n0];
            u64 bv0 = pack2(b4.x, b4.x), bv1 = pack2(b4.y, b4.y);
            u64 bv2 = pack2(b4.z, b4.z), bv3 = pack2(b4.w, b4.w);
            #pragma unroll
            for (int mp = 0; mp < 4; mp++) {
                acc[mp][0] = ffma2(av[mp], bv0, acc[mp][0]);
                acc[mp][1] = ffma2(av[mp], bv1, acc[mp][1]);
                acc[mp][2] = ffma2(av[mp], bv2, acc[mp][2]);
                acc[mp][3] = ffma2(av[mp], bv3, acc[mp][3]);
            }
        }

        if (c < 7) {
            #pragma unroll
            for (int j = 0; j < 4; j++) {
                As[nxt][kq * 4 + j][rA]      = ((const float*)&a0)[j];
                As[nxt][kq * 4 + j][rA + 64] = ((const float*)&a1)[j];
            }
            *(float4*)&Bs[nxt][bk][bn] = b;
        }
        __syncthreads();
    }

    #pragma unroll
    for (int mp = 0; mp < 4; mp++) {
        float2 c0 = unpack2(acc[mp][0]), c1 = unpack2(acc[mp][1]);
        float2 c2 = unpack2(acc[mp][2]), c3 = unpack2(acc[mp][3]);
        float* o0 = out + (rowBase + m0 + 2 * mp) * (size_t)H_ + colBase + n0;
        float* o1 = o0 + H_;
        *(float4*)o0 = make_float4(c0.x, c1.x, c2.x, c3.x);
        *(float4*)o1 = make_float4(c0.y, c1.y, c2.y, c3.y);
    }
}

// ======================= Phase 2: recurrence =============================
// v4: R10 parameters (KREG 16 / KSM 16, regs 126) + float2 combine (R11's
// valid piece) + software-pipelined smem-W loop (stage w4/hv for i+1 before
// the FMA block of i, shortening the exposed LDS->pack->FMA chain).

#define RC_CH    8
#define RC_KR    32
#define RC_KREG  16
#define RC_KSM   16
#define RC_WSM_BYTES (RC_CH * RC_KSM * 64 * 16)   // 131072
#define RC_HS_BYTES  (2 * 256 * 4 * 4)            // 8192
#define RC_PS_BYTES  (RC_CH * 4 * 256 * 4)        // 32768
#define RC_SMEM (RC_WSM_BYTES + RC_HS_BYTES + RC_PS_BYTES)   // 172032

__global__ void __launch_bounds__(512, 1) ctrnn_rec_kernel(
    const float* __restrict__ hidden, const float* __restrict__ Whh,
    float* __restrict__ out, float* __restrict__ tail)
{
    extern __shared__ char smc[];
    float4* Wsm = (float4*)smc;                                // [128][64]
    float*  hsb = (float*)(smc + RC_WSM_BYTES);                // [2][256][4]
    float*  psb = (float*)(smc + RC_WSM_BYTES + RC_HS_BYTES);  // [8][4][256]
    const int t  = threadIdx.x;
    const int jg = t & 63;
    const int c  = t >> 6;
    const int col = t & 255;
    const int hf  = t >> 8;
    const int b0 = blockIdx.x * 4;
    const int k0 = c * RC_KR;

    // --- prologue: weights ---
    float4 wreg[RC_KREG];                 // rows k0..k0+15, cols 4jg..4jg+3
    #pragma unroll
    for (int i = 0; i < RC_KREG; i++)
        wreg[i] = *(const float4*)(Whh + (size_t)(k0 + i) * H_ + 4 * jg);
    #pragma unroll
    for (int i = 0; i < RC_KSM; i++)
        Wsm[(c * RC_KSM + i) * 64 + jg] =
            *(const float4*)(Whh + (size_t)(k0 + RC_KREG + i) * H_ + 4 * jg);
    // --- prologue: h0, batch-major ---
    if (t < 256) {
        float4 v;
        v.x = hidden[(b0 + 0) * H_ + t];
        v.y = hidden[(b0 + 1) * H_ + t];
        v.z = hidden[(b0 + 2) * H_ + t];
        v.w = hidden[(b0 + 3) * H_ + t];
        ((float4*)hsb)[t] = v;
    }
    __syncthreads();

    const int bA = 2 * hf, bB = 2 * hf + 1;
    const float4* WsmMe = Wsm + (size_t)c * RC_KSM * 64 + jg;

    for (int s = 0; s < S_; s++) {
        const float* hc = hsb + (s & 1) * 1024;
        float* hn = hsb + ((s & 1) ^ 1) * 1024;
        float* op = out + ((size_t)s * B_ + b0) * H_ + col;

        // Prefetch xp (consumed after the barrier; DRAM latency hidden).
        float xpA = op[bA * 256];
        float xpB = op[bB * 256];

        const ulonglong2* hc2 = (const ulonglong2*)hc;   // hc2[k] = (b01, b23)
        u64 acc[4][2];
        #pragma unroll
        for (int cc = 0; cc < 4; cc++) { acc[cc][0] = 0ULL; acc[cc][1] = 0ULL; }

        // Register-weight rows (dup on ALU).
        #pragma unroll
        for (int i = 0; i < RC_KREG; i++) {
            ulonglong2 hv = hc2[k0 + i];
            float4 w4 = wreg[i];
            u64 w0 = pack2(w4.x, w4.x), w1 = pack2(w4.y, w4.y);
            u64 w2 = pack2(w4.z, w4.z), w3 = pack2(w4.w, w4.w);
            acc[0][0] = ffma2(hv.x, w0, acc[0][0]);
            acc[0][1] = ffma2(hv.y, w0, acc[0][1]);
            acc[1][0] = ffma2(hv.x, w1, acc[1][0]);
            acc[1][1] = ffma2(hv.y, w1, acc[1][1]);
            acc[2][0] = ffma2(hv.x, w2, acc[2][0]);
            acc[2][1] = ffma2(hv.y, w2, acc[2][1]);
            acc[3][0] = ffma2(hv.x, w3, acc[3][0]);
            acc[3][1] = ffma2(hv.y, w3, acc[3][1]);
        }
        // Smem-weight rows, software-pipelined: stage i+1's W and h before
        // issuing i's FMAs so the LDS latency is covered by the FMA block.
        {
            float4 w4n = WsmMe[0];
            ulonglong2 hvn = hc2[k0 + RC_KREG];
            #pragma unroll
            for (int i = 0; i < RC_KSM; i++) {
                float4 w4 = w4n;
                ulonglong2 hv = hvn;
                if (i + 1 < RC_KSM) {
                    w4n = WsmMe[(i + 1) * 64];
                    hvn = hc2[k0 + RC_KREG + i + 1];
                }
                u64 w0 = pack2(w4.x, w4.x), w1 = pack2(w4.y, w4.y);
                u64 w2 = pack2(w4.z, w4.z), w3 = pack2(w4.w, w4.w);
                acc[0][0] = ffma2(hv.x, w0, acc[0][0]);
                acc[0][1] = ffma2(hv.y, w0, acc[0][1]);
                acc[1][0] = ffma2(hv.x, w1, acc[1][0]);
                acc[1][1] = ffma2(hv.y, w1, acc[1][1]);
                acc[2][0] = ffma2(hv.x, w2, acc[2][0]);
                acc[2][1] = ffma2(hv.y, w2, acc[2][1]);
                acc[3][0] = ffma2(hv.x, w3, acc[3][0]);
                acc[3][1] = ffma2(hv.y, w3, acc[3][1]);
            }
        }

        // Partials: ps[c][b][col], per-batch float4 stores at 4*jg.
        {
            float2 u0a = unpack2(acc[0][0]), u1a = unpack2(acc[1][0]);
            float2 u2a = unpack2(acc[2][0]), u3a = unpack2(acc[3][0]);
            float2 u0b = unpack2(acc[0][1]), u1b = unpack2(acc[1][1]);
            float2 u2b = unpack2(acc[2][1]), u3b = unpack2(acc[3][1]);
            *(float4*)(psb + (c * 4 + 0) * 256 + 4 * jg) =
                make_float4(u0a.x, u1a.x, u2a.x, u3a.x);
            *(float4*)(psb + (c * 4 + 1) * 256 + 4 * jg) =
                make_float4(u0a.y, u1a.y, u2a.y, u3a.y);
            *(float4*)(psb + (c * 4 + 2) * 256 + 4 * jg) =
                make_float4(u0b.x, u1b.x, u2b.x, u3b.x);
            *(float4*)(psb + (c * 4 + 3) * 256 + 4 * jg) =
                make_float4(u0b.y, u1b.y, u2b.y, u3b.y);
        }
        __syncthreads();

        // Combine: thread (col, hf) finalizes batches bA, bB of its col.
        {
            float sA = 0.0f, sB = 0.0f;
            #pragma unroll
            for (int cc = 0; cc < RC_CH; cc++) {
                sA += psb[(cc * 4 + bA) * 256 + col];
                sB += psb[(cc * 4 + bB) * 256 + col];
            }
            // Adjacent batch pair -> one LDS.64 / STS.64.
            float2 ho = *(const float2*)(hc + col * 4 + bA);
            float hnA = 0.8f * ho.x + 0.2f * fmaxf(xpA + sA, 0.0f);
            float hnB = 0.8f * ho.y + 0.2f * fmaxf(xpB + sB, 0.0f);
            *(float2*)(hn + col * 4 + bA) = make_float2(hnA, hnB);
            op[bA * 256] = hnA;
            op[bB * 256] = hnB;
        }
        __syncthreads();
    }

    if (tail) {
        // Final h sits in buffer 0 (step s=1023 wrote buffer (1023&1)^1 = 0).
        float2 hf2 = *(const float2*)(hsb + col * 4 + bA);
        tail[(size_t)(b0 + bA) * H_ + col] = hf2.x;
        tail[(size_t)(b0 + bB) * H_ + col] = hf2.y;
    }
}

// ============================== launch ===================================

extern "C" void kernel_launch(void* const* d_in, const int* in_sizes, int n_in,
                              void* d_out, int out_size) {
    const float* input  = (const float*)d_in[0];
    const float* hidden = (const float*)d_in[1];
    const float* Win    = (const float*)d_in[2];
    const float* bin    = (const float*)d_in[3];
    const float* Whh    = (const float*)d_in[4];
    const float* bhh    = (const float*)d_in[5];
    float* out = (float*)d_out;

    cudaFuncSetAttribute(ctrnn_rec_kernel,
                         cudaFuncAttributeMaxDynamicSharedMemorySize, RC_SMEM);

    dim3 g(4096, 4);
    xproj_kernel<<<g, 256>>>(input, Win, bin, bhh, out);

    long long main_elems = (long long)S_ * B_ * H_;
    float* tail = ((long long)out_size > main_elems) ? (out + main_elems) : nullptr;
    ctrnn_rec_kernel<<<128, 512, RC_SMEM>>>(hidden, Whh, out, tail);
}

// round 14
// speedup vs baseline: 1.6409x; 1.6409x over previous
#include <cuda_runtime.h>
#include <cstdint>

// Problem constants: SEQ=1024, BATCH=512, IN=128, HID=256, alpha=0.2
#define S_  1024
#define B_  512
#define IN_ 128
#define H_  256

typedef unsigned long long u64;

__device__ __forceinline__ u64 ffma2(u64 a, u64 b, u64 c) {
    u64 d;
    asm("fma.rn.f32x2 %0, %1, %2, %3;" : "=l"(d) : "l"(a), "l"(b), "l"(c));
    return d;
}
__device__ __forceinline__ u64 pack2(float x, float y) {
    u64 r;
    asm("mov.b64 %0, {%1, %2};" : "=l"(r) : "f"(x), "f"(y));
    return r;
}
__device__ __forceinline__ float2 unpack2(u64 v) {
    float2 r;
    asm("mov.b64 {%0, %1}, %2;" : "=f"(r.x), "=f"(r.y) : "l"(v));
    return r;
}

// ======================= Phase 1: x_proj GEMM ============================
// (unchanged — ~0.65 ms on healthy clock)
// out[(s*B + b)*H + h] = input[s,b,:] . W_in[:,h] + b_in[h] + b_hh[h]
// [M=524288, K=128] @ [128, 256]. Chunked-K (KC=16, 8 chunks) double-
// buffered; block tile 128x64, 256 threads, thread tile 4 row-pairs x 4
// cols (f32x2). Static smem 25KB, 3 blocks/SM.

#define XP_KC   16
#define XP_AST  132

__global__ void __launch_bounds__(256, 3) xproj_kernel(
    const float* __restrict__ input, const float* __restrict__ Win,
    const float* __restrict__ bin, const float* __restrict__ bhh,
    float* __restrict__ out)
{
    __shared__ float As[2][XP_KC][XP_AST];
    __shared__ float Bs[2][XP_KC][64];

    const int t = threadIdx.x;
    const size_t rowBase = (size_t)blockIdx.x * 128;
    const int colBase = blockIdx.y * 64;

    const int tx = t & 15, ty = t >> 4;
    const int m0 = ty * 8, n0 = tx * 4;

    const int rA = t >> 2;
    const int kq = t & 3;
    const int bk = t >> 4;
    const int bn = (t & 15) * 4;

    const float* aSrc0 = input + (rowBase + rA) * IN_ + kq * 4;
    const float* aSrc1 = input + (rowBase + rA + 64) * IN_ + kq * 4;
    const float* bSrc  = Win + (size_t)bk * H_ + colBase + bn;

    u64 acc[4][4];
    {
        float4 bi = *(const float4*)(bin + colBase + n0);
        float4 bh = *(const float4*)(bhh + colBase + n0);
        float bias[4] = {bi.x + bh.x, bi.y + bh.y, bi.z + bh.z, bi.w + bh.w};
        #pragma unroll
        for (int j = 0; j < 4; j++) {
            u64 bb = pack2(bias[j], bias[j]);
            #pragma unroll
            for (int mp = 0; mp < 4; mp++) acc[mp][j] = bb;
        }
    }

    {
        float4 a0 = *(const float4*)(aSrc0);
        float4 a1 = *(const float4*)(aSrc1);
        float4 b  = *(const float4*)(bSrc);
        #pragma unroll
        for (int j = 0; j < 4; j++) {
            As[0][kq * 4 + j][rA]      = ((const float*)&a0)[j];
            As[0][kq * 4 + j][rA + 64] = ((const float*)&a1)[j];
        }
        *(float4*)&Bs[0][bk][bn] = b;
    }
    __syncthreads();

    #pragma unroll 1
    for (int c = 0; c < 8; c++) {
        const int cur = c & 1, nxt = cur ^ 1;
        float4 a0, a1, b;
        if (c < 7) {
            a0 = *(const float4*)(aSrc0 + (c + 1) * XP_KC);
            a1 = *(const float4*)(aSrc1 + (c + 1) * XP_KC);
            b  = *(const float4*)(bSrc + (size_t)(c + 1) * XP_KC * H_);
        }

        #pragma unroll
        for (int k = 0; k < XP_KC; k++) {
            ulonglong2 ap0 = *(const ulonglong2*)&As[cur][k][m0];
            ulonglong2 ap1 = *(const ulonglong2*)&As[cur][k][m0 + 4];
            u64 av[4] = {ap0.x, ap0.y, ap1.x, ap1.y};
            float4 b4 = *(const float4*)&Bs[cur][k][n0];
            u64 bv0 = pack2(b4.x, b4.x), bv1 = pack2(b4.y, b4.y);
            u64 bv2 = pack2(b4.z, b4.z), bv3 = pack2(b4.w, b4.w);
            #pragma unroll
            for (int mp = 0; mp < 4; mp++) {
                acc[mp][0] = ffma2(av[mp], bv0, acc[mp][0]);
                acc[mp][1] = ffma2(av[mp], bv1, acc[mp][1]);
                acc[mp][2] = ffma2(av[mp], bv2, acc[mp][2]);
                acc[mp][3] = ffma2(av[mp], bv3, acc[mp][3]);
            }
        }

        if (c < 7) {
            #pragma unroll
            for (int j = 0; j < 4; j++) {
                As[nxt][kq * 4 + j][rA]      = ((const float*)&a0)[j];
                As[nxt][kq * 4 + j][rA + 64] = ((const float*)&a1)[j];
            }
            *(float4*)&Bs[nxt][bk][bn] = b;
        }
        __syncthreads();
    }

    #pragma unroll
    for (int mp = 0; mp < 4; mp++) {
        float2 c0 = unpack2(acc[mp][0]), c1 = unpack2(acc[mp][1]);
        float2 c2 = unpack2(acc[mp][2]), c3 = unpack2(acc[mp][3]);
        float* o0 = out + (rowBase + m0 + 2 * mp) * (size_t)H_ + colBase + n0;
        float* o1 = o0 + H_;
        *(float4*)o0 = make_float4(c0.x, c1.x, c2.x, c3.x);
        *(float4*)o1 = make_float4(c0.y, c1.y, c2.y, c3.y);
    }
}

// ======================= Phase 2: recurrence =============================
// v5 = R10 structure exactly (KREG 16 / KSM 16, plain inner loops) plus the
// float2 combine (one LDS.64/STS.64 for the adjacent batch pair), which R12
// showed to be cycle-neutral-or-better. No software pipelining (neutral).

#define RC_CH    8
#define RC_KR    32
#define RC_KREG  16
#define RC_KSM   16
#define RC_WSM_BYTES (RC_CH * RC_KSM * 64 * 16)   // 131072
#define RC_HS_BYTES  (2 * 256 * 4 * 4)            // 8192
#define RC_PS_BYTES  (RC_CH * 4 * 256 * 4)        // 32768
#define RC_SMEM (RC_WSM_BYTES + RC_HS_BYTES + RC_PS_BYTES)   // 172032

__global__ void __launch_bounds__(512, 1) ctrnn_rec_kernel(
    const float* __restrict__ hidden, const float* __restrict__ Whh,
    float* __restrict__ out, float* __restrict__ tail)
{
    extern __shared__ char smc[];
    float4* Wsm = (float4*)smc;                                // [128][64]
    float*  hsb = (float*)(smc + RC_WSM_BYTES);                // [2][256][4]
    float*  psb = (float*)(smc + RC_WSM_BYTES + RC_HS_BYTES);  // [8][4][256]
    const int t  = threadIdx.x;
    const int jg = t & 63;
    const int c  = t >> 6;
    const int col = t & 255;
    const int hf  = t >> 8;
    const int b0 = blockIdx.x * 4;
    const int k0 = c * RC_KR;

    // --- prologue: weights ---
    float4 wreg[RC_KREG];                 // rows k0..k0+15, cols 4jg..4jg+3
    #pragma unroll
    for (int i = 0; i < RC_KREG; i++)
        wreg[i] = *(const float4*)(Whh + (size_t)(k0 + i) * H_ + 4 * jg);
    #pragma unroll
    for (int i = 0; i < RC_KSM; i++)
        Wsm[(c * RC_KSM + i) * 64 + jg] =
            *(const float4*)(Whh + (size_t)(k0 + RC_KREG + i) * H_ + 4 * jg);
    // --- prologue: h0, batch-major ---
    if (t < 256) {
        float4 v;
        v.x = hidden[(b0 + 0) * H_ + t];
        v.y = hidden[(b0 + 1) * H_ + t];
        v.z = hidden[(b0 + 2) * H_ + t];
        v.w = hidden[(b0 + 3) * H_ + t];
        ((float4*)hsb)[t] = v;
    }
    __syncthreads();

    const int bA = 2 * hf, bB = 2 * hf + 1;

    for (int s = 0; s < S_; s++) {
        const float* hc = hsb + (s & 1) * 1024;
        float* hn = hsb + ((s & 1) ^ 1) * 1024;
        float* op = out + ((size_t)s * B_ + b0) * H_ + col;

        // Prefetch xp (consumed after the barrier; DRAM latency hidden).
        float xpA = op[bA * 256];
        float xpB = op[bB * 256];

        const ulonglong2* hc2 = (const ulonglong2*)hc;   // hc2[k] = (b01, b23)
        u64 acc[4][2];
        #pragma unroll
        for (int cc = 0; cc < 4; cc++) { acc[cc][0] = 0ULL; acc[cc][1] = 0ULL; }

        // Register-weight rows (dup on ALU).
        #pragma unroll
        for (int i = 0; i < RC_KREG; i++) {
            ulonglong2 hv = hc2[k0 + i];
            float4 w4 = wreg[i];
            u64 w0 = pack2(w4.x, w4.x), w1 = pack2(w4.y, w4.y);
            u64 w2 = pack2(w4.z, w4.z), w3 = pack2(w4.w, w4.w);
            acc[0][0] = ffma2(hv.x, w0, acc[0][0]);
            acc[0][1] = ffma2(hv.y, w0, acc[0][1]);
            acc[1][0] = ffma2(hv.x, w1, acc[1][0]);
            acc[1][1] = ffma2(hv.y, w1, acc[1][1]);
            acc[2][0] = ffma2(hv.x, w2, acc[2][0]);
            acc[2][1] = ffma2(hv.y, w2, acc[2][1]);
            acc[3][0] = ffma2(hv.x, w3, acc[3][0]);
            acc[3][1] = ffma2(hv.y, w3, acc[3][1]);
        }
        // Smem-weight rows (conflict-free LDS.128, dup on ALU).
        #pragma unroll
        for (int i = 0; i < RC_KSM; i++) {
            float4 w4 = Wsm[(c * RC_KSM + i) * 64 + jg];
            ulonglong2 hv = hc2[k0 + RC_KREG + i];
            u64 w0 = pack2(w4.x, w4.x), w1 = pack2(w4.y, w4.y);
            u64 w2 = pack2(w4.z, w4.z), w3 = pack2(w4.w, w4.w);
            acc[0][0] = ffma2(hv.x, w0, acc[0][0]);
            acc[0][1] = ffma2(hv.y, w0, acc[0][1]);
            acc[1][0] = ffma2(hv.x, w1, acc[1][0]);
            acc[1][1] = ffma2(hv.y, w1, acc[1][1]);
            acc[2][0] = ffma2(hv.x, w2, acc[2][0]);
            acc[2][1] = ffma2(hv.y, w2, acc[2][1]);
            acc[3][0] = ffma2(hv.x, w3, acc[3][0]);
            acc[3][1] = ffma2(hv.y, w3, acc[3][1]);
        }

        // Partials: ps[c][b][col], per-batch float4 stores at 4*jg.
        {
            float2 u0a = unpack2(acc[0][0]), u1a = unpack2(acc[1][0]);
            float2 u2a = unpack2(acc[2][0]), u3a = unpack2(acc[3][0]);
            float2 u0b = unpack2(acc[0][1]), u1b = unpack2(acc[1][1]);
            float2 u2b = unpack2(acc[2][1]), u3b = unpack2(acc[3][1]);
            *(float4*)(psb + (c * 4 + 0) * 256 + 4 * jg) =
                make_float4(u0a.x, u1a.x, u2a.x, u3a.x);
            *(float4*)(psb + (c * 4 + 1) * 256 + 4 * jg) =
                make_float4(u0a.y, u1a.y, u2a.y, u3a.y);
            *(float4*)(psb + (c * 4 + 2) * 256 + 4 * jg) =
                make_float4(u0b.x, u1b.x, u2b.x, u3b.x);
            *(float4*)(psb + (c * 4 + 3) * 256 + 4 * jg) =
                make_float4(u0b.y, u1b.y, u2b.y, u3b.y);
        }
        __syncthreads();

        // Combine: thread (col, hf) finalizes batches bA, bB of its col.
        {
            float sA = 0.0f, sB = 0.0f;
            #pragma unroll
            for (int cc = 0; cc < RC_CH; cc++) {
                sA += psb[(cc * 4 + bA) * 256 + col];
                sB += psb[(cc * 4 + bB) * 256 + col];
            }
            // Adjacent batch pair -> one LDS.64 / STS.64.
            float2 ho = *(const float2*)(hc + col * 4 + bA);
            float hnA = 0.8f * ho.x + 0.2f * fmaxf(xpA + sA, 0.0f);
            float hnB = 0.8f * ho.y + 0.2f * fmaxf(xpB + sB, 0.0f);
            *(float2*)(hn + col * 4 + bA) = make_float2(hnA, hnB);
            op[bA * 256] = hnA;
            op[bB * 256] = hnB;
        }
        __syncthreads();
    }

    if (tail) {
        // Final h sits in buffer 0 (step s=1023 wrote buffer (1023&1)^1 = 0).
        float2 hf2 = *(const float2*)(hsb + col * 4 + bA);
        tail[(size_t)(b0 + bA) * H_ + col] = hf2.x;
        tail[(size_t)(b0 + bB) * H_ + col] = hf2.y;
    }
}

// ============================== launch ===================================

extern "C" void kernel_launch(void* const* d_in, const int* in_sizes, int n_in,
                              void* d_out, int out_size) {
    const float* input  = (const float*)d_in[0];
    const float* hidden = (const float*)d_in[1];
    const float* Win    = (const float*)d_in[2];
    const float* bin    = (const float*)d_in[3];
    const float* Whh    = (const float*)d_in[4];
    const float* bhh    = (const float*)d_in[5];
    float* out = (float*)d_out;

    cudaFuncSetAttribute(ctrnn_rec_kernel,
                         cudaFuncAttributeMaxDynamicSharedMemorySize, RC_SMEM);

    dim3 g(4096, 4);
    xproj_kernel<<<g, 256>>>(input, Win, bin, bhh, out);

    long long main_elems = (long long)S_ * B_ * H_;
    float* tail = ((long long)out_size > main_elems) ? (out + main_elems) : nullptr;
    ctrnn_rec_kernel<<<128, 512, RC_SMEM>>>(hidden, Whh, out, tail);
}